// round 14
// baseline (speedup 1.0000x reference)
#include <cuda_runtime.h>
#include <cuda_bf16.h>
#include <cuda_fp16.h>
#include <math.h>
#include <stdint.h>

// Problem constants
#define BATCH 4
#define SEQ   4096
#define DIM   128
#define TOK   (BATCH*SEQ)   // 16384

#define BM 128
#define BN 128
#define PADK 132    // fp32 smem row pitch for proj (floats)
#define SB   136    // fp16 smem row pitch (272 B)
#define LOG2E 1.4426950408889634f

// ---------------- device scratch (allocation-free: __device__ globals) -------
__device__ __half g_Qh[TOK*DIM];                       // Q' = log2e * Q, fp16
__device__ __half g_Kh[TOK*DIM];                       // K, fp16
__device__ float g_V[TOK*DIM];                         // V fp32
__device__ float g_S[BATCH*SEQ];                       // row sums of 2^(s')
__device__ float g_C[BATCH*SEQ];                       // column weights
__device__ __nv_bfloat16 g_E[(size_t)BATCH*SEQ*SEQ];   // 2^(s'), bf16, 134 MB

// ---------------- helpers ----------------------------------------------------
__device__ __forceinline__ float ex2f(float x) {
    float y; asm("ex2.approx.f32 %0, %1;" : "=f"(y) : "f"(x)); return y;
}
__device__ __forceinline__ float tf32_round(float x) {
    uint32_t u;
    asm("cvt.rna.tf32.f32 %0, %1;" : "=r"(u) : "f"(x));
    return __uint_as_float(u);
}

#define MMA_TF32(C, A, B)                                                     \
  asm volatile("mma.sync.aligned.m16n8k8.row.col.f32.tf32.tf32.f32 "          \
    "{%0,%1,%2,%3}, {%4,%5,%6,%7}, {%8,%9}, {%0,%1,%2,%3};"                   \
    : "+f"((C)[0]), "+f"((C)[1]), "+f"((C)[2]), "+f"((C)[3])                  \
    : "r"((A)[0]), "r"((A)[1]), "r"((A)[2]), "r"((A)[3]),                     \
      "r"((B)[0]), "r"((B)[1]))

#define MMA_FP16(C, A, B0, B1)                                                \
  asm volatile("mma.sync.aligned.m16n8k16.row.col.f32.f16.f16.f32 "           \
    "{%0,%1,%2,%3}, {%4,%5,%6,%7}, {%8,%9}, {%0,%1,%2,%3};"                   \
    : "+f"((C)[0]), "+f"((C)[1]), "+f"((C)[2]), "+f"((C)[3])                  \
    : "r"((A)[0]), "r"((A)[1]), "r"((A)[2]), "r"((A)[3]),                     \
      "r"(B0), "r"(B1))

#define LDMX4(R, ADDR)                                                        \
  asm volatile("ldmatrix.sync.aligned.m8n8.x4.shared.b16 {%0,%1,%2,%3}, [%4];"\
    : "=r"((R)[0]), "=r"((R)[1]), "=r"((R)[2]), "=r"((R)[3]) : "r"(ADDR))

#define CP_ASYNC16(dst, src)                                                  \
  asm volatile("cp.async.cg.shared.global [%0], [%1], 16;" :: "r"(dst), "l"(src))
#define CP_COMMIT() asm volatile("cp.async.commit_group;")
#define CP_WAIT1()  asm volatile("cp.async.wait_group 1;")
#define CP_WAIT0()  asm volatile("cp.async.wait_group 0;")

// ---------------- K1: QKV projection (tf32 mma, z-loop, RNA rounding) --------
// Also zeroes g_S/g_C (own 128-slice) and out (blocks 0-1) — replaces zero_kernel.
__global__ __launch_bounds__(256, 1)
void proj_kernel(const float* __restrict__ x,
                 const float* __restrict__ Wq, const float* __restrict__ bq,
                 const float* __restrict__ Wk, const float* __restrict__ bk,
                 const float* __restrict__ Wv, const float* __restrict__ bv,
                 float* __restrict__ outz) {
    extern __shared__ float sm[];
    float* As = sm;                   // [BM][PADK]
    float* Wb[2] = { sm + BM*PADK, sm + 2*BM*PADK };

    const int rowBase = blockIdx.x * BM;
    const int tid = threadIdx.x;

    if (tid < 128) {
        g_S[rowBase + tid] = 0.0f;
        g_C[rowBase + tid] = 0.0f;
    }
    if (blockIdx.x < 2) outz[blockIdx.x*256 + tid] = 0.0f;

    #pragma unroll
    for (int j = 0; j < 16; j++) {
        int c = tid + j*256;          // 4096 chunks of 16B
        int r = c >> 5, k4 = (c & 31) * 4;
        CP_ASYNC16((uint32_t)__cvta_generic_to_shared(As + r*PADK + k4),
                   x + (size_t)(rowBase + r)*DIM + k4);
        CP_ASYNC16((uint32_t)__cvta_generic_to_shared(Wb[0] + r*PADK + k4),
                   Wq + r*DIM + k4);
    }
    CP_COMMIT();
    #pragma unroll
    for (int j = 0; j < 16; j++) {
        int c = tid + j*256;
        int r = c >> 5, k4 = (c & 31) * 4;
        CP_ASYNC16((uint32_t)__cvta_generic_to_shared(Wb[1] + r*PADK + k4),
                   Wk + r*DIM + k4);
    }
    CP_COMMIT();
    CP_WAIT1();   // As + W0 arrived
    #pragma unroll
    for (int j = 0; j < 16; j++) {
        int c = tid + j*256;
        int r = c >> 5, k4 = (c & 31) * 4;
        float4* p = (float4*)(As + r*PADK + k4);
        float4 v = *p;
        v.x = tf32_round(v.x); v.y = tf32_round(v.y);
        v.z = tf32_round(v.z); v.w = tf32_round(v.w);
        *p = v;
        float4* q = (float4*)(Wb[0] + r*PADK + k4);
        v = *q;
        v.x = tf32_round(v.x); v.y = tf32_round(v.y);
        v.z = tf32_round(v.z); v.w = tf32_round(v.w);
        *q = v;
    }
    __syncthreads();

    const int lane = tid & 31, warp = tid >> 5;
    const int wm = (warp >> 1) * 32;
    const int wn = (warp & 1) * 64;
    const int g = lane >> 2, t = lane & 3;

    #pragma unroll 1
    for (int z = 0; z < 3; z++) {
        float* Bs = Wb[z == 1];
        const float* bias = (z == 0) ? bq : (z == 1) ? bk : bv;

        float c[2][8][4];
        #pragma unroll
        for (int mt = 0; mt < 2; mt++)
            #pragma unroll
            for (int nt = 0; nt < 8; nt++)
                #pragma unroll
                for (int j = 0; j < 4; j++) c[mt][nt][j] = 0.0f;

        #pragma unroll
        for (int kk = 0; kk < DIM/8; kk++) {
            const int kb = kk*8;
            uint32_t a[2][4], bb[8][2];
            #pragma unroll
            for (int mt = 0; mt < 2; mt++) {
                const float* p = As + (wm + mt*16 + g)*PADK + kb + t;
                a[mt][0] = __float_as_uint(p[0]);
                a[mt][1] = __float_as_uint(p[8*PADK]);
                a[mt][2] = __float_as_uint(p[4]);
                a[mt][3] = __float_as_uint(p[8*PADK + 4]);
            }
            #pragma unroll
            for (int nt = 0; nt < 8; nt++) {
                const float* p = Bs + (wn + nt*8 + g)*PADK + kb + t;
                bb[nt][0] = __float_as_uint(p[0]);
                bb[nt][1] = __float_as_uint(p[4]);
            }
            #pragma unroll
            for (int mt = 0; mt < 2; mt++)
                #pragma unroll
                for (int nt = 0; nt < 8; nt++)
                    MMA_TF32(c[mt][nt], a[mt], bb[nt]);
        }

        const float scale = (z == 0) ? LOG2E : 1.0f;
        __half* oh = (z == 0) ? g_Qh : g_Kh;
        #pragma unroll
        for (int mt = 0; mt < 2; mt++) {
            const int r0 = rowBase + wm + mt*16 + g;
            #pragma unroll
            for (int nt = 0; nt < 8; nt++) {
                const int cn = wn + nt*8 + 2*t;
                float b0 = __ldg(&bias[cn]), b1 = __ldg(&bias[cn+1]);
                float v00 = (c[mt][nt][0] + b0) * scale, v01 = (c[mt][nt][1] + b1) * scale;
                float v10 = (c[mt][nt][2] + b0) * scale, v11 = (c[mt][nt][3] + b1) * scale;
                if (z < 2) {
                    *(__half2*)(oh + (size_t)r0*DIM + cn)     = __floats2half2_rn(v00, v01);
                    *(__half2*)(oh + (size_t)(r0+8)*DIM + cn) = __floats2half2_rn(v10, v11);
                } else {
                    *(float2*)(g_V + (size_t)r0*DIM + cn)     = make_float2(v00, v01);
                    *(float2*)(g_V + (size_t)(r0+8)*DIM + cn) = make_float2(v10, v11);
                }
            }
        }

        if (z == 0) {
            __syncthreads();
            #pragma unroll
            for (int j = 0; j < 16; j++) {
                int cc = tid + j*256;
                int r = cc >> 5, k4 = (cc & 31) * 4;
                CP_ASYNC16((uint32_t)__cvta_generic_to_shared(Wb[0] + r*PADK + k4),
                           Wv + r*DIM + k4);
            }
            CP_COMMIT();
            CP_WAIT1();                         // W1 (Wk) arrived
            #pragma unroll
            for (int j = 0; j < 16; j++) {
                int cc = tid + j*256;
                int r = cc >> 5, k4 = (cc & 31) * 4;
                float4* p = (float4*)(Wb[1] + r*PADK + k4);
                float4 v = *p;
                v.x = tf32_round(v.x); v.y = tf32_round(v.y);
                v.z = tf32_round(v.z); v.w = tf32_round(v.w);
                *p = v;
            }
            __syncthreads();
        } else if (z == 1) {
            __syncthreads();
            CP_WAIT0();                         // Wv arrived
            #pragma unroll
            for (int j = 0; j < 16; j++) {
                int cc = tid + j*256;
                int r = cc >> 5, k4 = (cc & 31) * 4;
                float4* p = (float4*)(Wb[0] + r*PADK + k4);
                float4 v = *p;
                v.x = tf32_round(v.x); v.y = tf32_round(v.y);
                v.z = tf32_round(v.z); v.w = tf32_round(v.w);
                *p = v;
            }
            __syncthreads();
        }
    }
}

// ---------------- K2: E = 2^(Q'K^T) (fp16 mma + ldmatrix), rowsums -----------
// Each block handles FOUR adjacent 128-col tiles against one resident Q tile.
// Next K tile prefetched via cp.async overlapped with current tile's E-flush.
#define CTILES 4
__global__ __launch_bounds__(256, 2)
void score_kernel() {
    extern __shared__ __half smh[];
    __half* Qs = smh;             // [BM][SB]
    __half* Ks = smh +   BM*SB;   // [BN][SB]
    __nv_bfloat16* Es = (__nv_bfloat16*)(smh + 2*BM*SB);   // [BM][SB] staging

    const int b = blockIdx.z;
    const int rowBase = blockIdx.y * BM;
    const int colBase0 = blockIdx.x * (CTILES*BN);
    const int tid = threadIdx.x;

    {
        const uint4* Qg = (const uint4*)(g_Qh + ((size_t)b*SEQ + rowBase)*DIM);
        const uint4* Kg = (const uint4*)(g_Kh + ((size_t)b*SEQ + colBase0)*DIM);
        #pragma unroll
        for (int i = tid; i < BM*16; i += 256) {
            int r = i >> 4, ch = i & 15;
            *(uint4*)(Qs + r*SB + ch*8) = Qg[r*16 + ch];
            *(uint4*)(Ks + r*SB + ch*8) = Kg[r*16 + ch];
        }
    }
    __syncthreads();

    const int lane = tid & 31, warp = tid >> 5;
    const int wm = (warp >> 1) * 32;
    const int wn = (warp & 1) * 64;

    const int aRow = wm + (lane & 15);
    const int aCol = (lane >> 4) << 3;
    uint32_t aAddr = (uint32_t)__cvta_generic_to_shared(Qs + aRow*SB + aCol);
    const int bRow = wn + (lane & 7) + ((lane >> 4) << 3);
    const int bCol = ((lane >> 3) & 1) << 3;
    uint32_t bAddr = (uint32_t)__cvta_generic_to_shared(Ks + bRow*SB + bCol);
    const uint32_t ksBase = (uint32_t)__cvta_generic_to_shared(Ks);

    const int g = lane >> 2, t = lane & 3;

    #pragma unroll 1
    for (int ct = 0; ct < CTILES; ct++) {
        const int colBase = colBase0 + ct*BN;

        float c[2][8][4];
        #pragma unroll
        for (int mt = 0; mt < 2; mt++)
            #pragma unroll
            for (int nt = 0; nt < 8; nt++)
                #pragma unroll
                for (int j = 0; j < 4; j++) c[mt][nt][j] = 0.0f;

        #pragma unroll
        for (int kk = 0; kk < DIM/16; kk++) {
            uint32_t a[2][4], bb[4][4];
            #pragma unroll
            for (int mt = 0; mt < 2; mt++)
                LDMX4(a[mt], aAddr + (mt*16*SB)*2 + kk*32);
            #pragma unroll
            for (int ntp = 0; ntp < 4; ntp++)
                LDMX4(bb[ntp], bAddr + (ntp*16*SB)*2 + kk*32);
            #pragma unroll
            for (int mt = 0; mt < 2; mt++)
                #pragma unroll
                for (int nt = 0; nt < 8; nt++)
                    MMA_FP16(c[mt][nt], a[mt], bb[nt>>1][(nt&1)*2], bb[nt>>1][(nt&1)*2+1]);
        }

        // epilogue: ex2, rowsum, stage bf16 tile in smem (conflict-free STS)
        #pragma unroll
        for (int mt = 0; mt < 2; mt++) {
            const int lr0 = wm + mt*16 + g;       // tile-local rows
            const int lr1 = lr0 + 8;
            float rs0 = 0.0f, rs1 = 0.0f;
            #pragma unroll
            for (int nt = 0; nt < 8; nt++) {
                const int cn = wn + nt*8 + 2*t;
                float e0 = ex2f(c[mt][nt][0]);
                float e1 = ex2f(c[mt][nt][1]);
                float e2 = ex2f(c[mt][nt][2]);
                float e3 = ex2f(c[mt][nt][3]);
                rs0 += e0 + e1;
                rs1 += e2 + e3;
                *(__nv_bfloat162*)(Es + lr0*SB + cn) = __floats2bfloat162_rn(e0, e1);
                *(__nv_bfloat162*)(Es + lr1*SB + cn) = __floats2bfloat162_rn(e2, e3);
            }
            #pragma unroll
            for (int o = 1; o <= 2; o <<= 1) {
                rs0 += __shfl_xor_sync(0xffffffffu, rs0, o);
                rs1 += __shfl_xor_sync(0xffffffffu, rs1, o);
            }
            if (t == 0) {
                atomicAdd(&g_S[b*SEQ + rowBase + lr0], rs0);
                atomicAdd(&g_S[b*SEQ + rowBase + lr1], rs1);
            }
        }
        __syncthreads();   // Es complete; all warps done reading Ks (mma finished)

        // prefetch next K tile (overlaps the E-flush below; disjoint buffers)
        if (ct + 1 < CTILES) {
            const __half* Kn = g_Kh + ((size_t)b*SEQ + colBase0 + (ct+1)*BN)*DIM;
            #pragma unroll
            for (int j = 0; j < 8; j++) {
                int idx = tid + j*256;
                int r = idx >> 4, ch = idx & 15;
                CP_ASYNC16(ksBase + (uint32_t)(r*SB + ch*8)*2,
                           Kn + (size_t)r*DIM + ch*8);
            }
            CP_COMMIT();
        }

        // coalesced flush: 2048 uint4 / 256 threads = 8 per thread
        #pragma unroll
        for (int j = 0; j < 8; j++) {
            int idx = tid + j*256;
            int r = idx >> 4, ch = idx & 15;
            uint4 v = *(const uint4*)(Es + r*SB + ch*8);
            *(uint4*)(g_E + ((size_t)b*SEQ + rowBase + r)*SEQ + colBase + ch*8) = v;
        }

        if (ct + 1 < CTILES) {
            CP_WAIT0();
            __syncthreads();   // new Ks visible; Es reusable (flush done per-thread)
        }
    }
}

// ---------------- K3: column-tiled colsum (K3_ROWS=512: halved atomics) ------
#define K3_ROWS 512
__global__ __launch_bounds__(256, 8)
void colsum_kernel() {
    __shared__ float invS[K3_ROWS];
    const int b = blockIdx.z;
    const int mBase = blockIdx.x * 512;          // 512 m's per block (2 per thread)
    const int nBase = blockIdx.y * K3_ROWS;
    const int tid = threadIdx.x;

    for (int i = tid; i < K3_ROWS; i += 256)
        invS[i] = 1.0f / g_S[b*SEQ + nBase + i];
    __syncthreads();

    const __nv_bfloat162* Ep =
        (const __nv_bfloat162*)(g_E + ((size_t)b*SEQ + nBase)*SEQ) + (mBase >> 1) + tid;
    const size_t strideV2 = SEQ / 2;

    float a0 = 0.f, a1 = 0.f, b0 = 0.f, b1 = 0.f;
    #pragma unroll 8
    for (int n = 0; n < K3_ROWS; n += 2) {
        float2 v0 = __bfloat1622float2(Ep[(size_t)n * strideV2]);
        float2 v1 = __bfloat1622float2(Ep[(size_t)(n+1) * strideV2]);
        a0 += v0.x * invS[n];   a1 += v0.y * invS[n];
        b0 += v1.x * invS[n+1]; b1 += v1.y * invS[n+1];
    }
    const int m = mBase + tid*2;
    atomicAdd(&g_C[b*SEQ + m],     (a0 + b0) * (1.0f/SEQ));
    atomicAdd(&g_C[b*SEQ + m + 1], (a1 + b1) * (1.0f/SEQ));
}

// ---------------- K4: out[b,d] = sum_m c[m] * V[b,m,d] -----------------------
// 512 blocks x 512 threads: 4 row-groups per block, smem tree reduction,
// one global atomic per (block, d).
__global__ __launch_bounds__(512, 4)
void out_kernel(float* __restrict__ out) {
    __shared__ float sred[3*DIM];
    const int b = blockIdx.y;
    const int mBase = blockIdx.x * 32;
    const int d = threadIdx.x & 127;
    const int h = threadIdx.x >> 7;     // 0..3
    const float* Vp = g_V + ((size_t)b*SEQ + mBase + h)*DIM + d;
    const float* Cp = g_C + b*SEQ + mBase + h;
    float acc = 0.0f;
    #pragma unroll
    for (int m = 0; m < 32; m += 4)
        acc += Cp[m] * Vp[(size_t)m*DIM];
    if (h) sred[(h-1)*DIM + d] = acc;
    __syncthreads();
    if (h == 0)
        atomicAdd(&out[b*DIM + d], acc + sred[d] + sred[DIM + d] + sred[2*DIM + d]);
}

// ---------------- launch -----------------------------------------------------
extern "C" void kernel_launch(void* const* d_in, const int* in_sizes, int n_in,
                              void* d_out, int out_size) {
    const float* x  = (const float*)d_in[0];
    const float* Wq = (const float*)d_in[1];
    const float* bq = (const float*)d_in[2];
    const float* Wk = (const float*)d_in[3];
    const float* bk = (const float*)d_in[4];
    const float* Wv = (const float*)d_in[5];
    const float* bv = (const float*)d_in[6];
    float* out = (float*)d_out;

    const int smemProj  = 3 * BM * PADK * sizeof(float);   // 202752 B
    const int smemScore = 3 * BM * SB * sizeof(__half);    // 104448 B
    cudaFuncSetAttribute(proj_kernel,  cudaFuncAttributeMaxDynamicSharedMemorySize, smemProj);
    cudaFuncSetAttribute(score_kernel, cudaFuncAttributeMaxDynamicSharedMemorySize, smemScore);

    proj_kernel<<<TOK/BM, 256, smemProj>>>(x, Wq, bq, Wk, bk, Wv, bv, out);

    dim3 gScore(SEQ/(CTILES*BN), SEQ/BM, BATCH);  // 8 x 32 x 4 = 1024 blocks
    score_kernel<<<gScore, 256, smemScore>>>();

    dim3 gCol(SEQ/512, SEQ/K3_ROWS, BATCH);       // 8 x 8 x 4 = 256 blocks
    colsum_kernel<<<gCol, 256>>>();

    dim3 gOut(SEQ/32, BATCH);                     // 128 x 4 = 512 blocks
    out_kernel<<<gOut, 512>>>(out);
}

// round 16
// speedup vs baseline: 1.0935x; 1.0935x over previous
#include <cuda_runtime.h>
#include <cuda_bf16.h>
#include <cuda_fp16.h>
#include <math.h>
#include <stdint.h>

// Problem constants
#define BATCH 4
#define SEQ   4096
#define DIM   128
#define TOK   (BATCH*SEQ)   // 16384

#define BM 128
#define BN 128
#define PADK 132    // fp32 smem row pitch for proj (floats)
#define SB   136    // fp16 smem row pitch (272 B)
#define LOG2E 1.4426950408889634f

// ---------------- device scratch (allocation-free: __device__ globals) -------
__device__ __half g_Qh[TOK*DIM];                       // Q' = log2e * Q, fp16
__device__ __half g_Kh[TOK*DIM];                       // K, fp16
__device__ float g_V[TOK*DIM];                         // V fp32
__device__ float g_S[BATCH*SEQ];                       // row sums of 2^(s')
__device__ float g_C[BATCH*SEQ];                       // column weights
__device__ __nv_bfloat16 g_E[(size_t)BATCH*SEQ*SEQ];   // 2^(s'), bf16, 134 MB

// ---------------- helpers ----------------------------------------------------
__device__ __forceinline__ float ex2f(float x) {
    float y; asm("ex2.approx.f32 %0, %1;" : "=f"(y) : "f"(x)); return y;
}
__device__ __forceinline__ float tf32_round(float x) {
    uint32_t u;
    asm("cvt.rna.tf32.f32 %0, %1;" : "=r"(u) : "f"(x));
    return __uint_as_float(u);
}

#define MMA_TF32(C, A, B)                                                     \
  asm volatile("mma.sync.aligned.m16n8k8.row.col.f32.tf32.tf32.f32 "          \
    "{%0,%1,%2,%3}, {%4,%5,%6,%7}, {%8,%9}, {%0,%1,%2,%3};"                   \
    : "+f"((C)[0]), "+f"((C)[1]), "+f"((C)[2]), "+f"((C)[3])                  \
    : "r"((A)[0]), "r"((A)[1]), "r"((A)[2]), "r"((A)[3]),                     \
      "r"((B)[0]), "r"((B)[1]))

#define MMA_FP16(C, A, B0, B1)                                                \
  asm volatile("mma.sync.aligned.m16n8k16.row.col.f32.f16.f16.f32 "           \
    "{%0,%1,%2,%3}, {%4,%5,%6,%7}, {%8,%9}, {%0,%1,%2,%3};"                   \
    : "+f"((C)[0]), "+f"((C)[1]), "+f"((C)[2]), "+f"((C)[3])                  \
    : "r"((A)[0]), "r"((A)[1]), "r"((A)[2]), "r"((A)[3]),                     \
      "r"(B0), "r"(B1))

#define LDMX4(R, ADDR)                                                        \
  asm volatile("ldmatrix.sync.aligned.m8n8.x4.shared.b16 {%0,%1,%2,%3}, [%4];"\
    : "=r"((R)[0]), "=r"((R)[1]), "=r"((R)[2]), "=r"((R)[3]) : "r"(ADDR))

#define CP_ASYNC16(dst, src)                                                  \
  asm volatile("cp.async.cg.shared.global [%0], [%1], 16;" :: "r"(dst), "l"(src))
#define CP_COMMIT() asm volatile("cp.async.commit_group;")
#define CP_WAIT1()  asm volatile("cp.async.wait_group 1;")
#define CP_WAIT0()  asm volatile("cp.async.wait_group 0;")

// ---------------- K1: QKV projection (tf32 mma, z-loop, RNA rounding) --------
// Also zeroes g_S/g_C (own 128-slice) and out (blocks 0-1) — replaces zero_kernel.
__global__ __launch_bounds__(256, 1)
void proj_kernel(const float* __restrict__ x,
                 const float* __restrict__ Wq, const float* __restrict__ bq,
                 const float* __restrict__ Wk, const float* __restrict__ bk,
                 const float* __restrict__ Wv, const float* __restrict__ bv,
                 float* __restrict__ outz) {
    extern __shared__ float sm[];
    float* As = sm;                   // [BM][PADK]
    float* Wb[2] = { sm + BM*PADK, sm + 2*BM*PADK };

    const int rowBase = blockIdx.x * BM;
    const int tid = threadIdx.x;

    if (tid < 128) {
        g_S[rowBase + tid] = 0.0f;
        g_C[rowBase + tid] = 0.0f;
    }
    if (blockIdx.x < 2) outz[blockIdx.x*256 + tid] = 0.0f;

    #pragma unroll
    for (int j = 0; j < 16; j++) {
        int c = tid + j*256;          // 4096 chunks of 16B
        int r = c >> 5, k4 = (c & 31) * 4;
        CP_ASYNC16((uint32_t)__cvta_generic_to_shared(As + r*PADK + k4),
                   x + (size_t)(rowBase + r)*DIM + k4);
        CP_ASYNC16((uint32_t)__cvta_generic_to_shared(Wb[0] + r*PADK + k4),
                   Wq + r*DIM + k4);
    }
    CP_COMMIT();
    #pragma unroll
    for (int j = 0; j < 16; j++) {
        int c = tid + j*256;
        int r = c >> 5, k4 = (c & 31) * 4;
        CP_ASYNC16((uint32_t)__cvta_generic_to_shared(Wb[1] + r*PADK + k4),
                   Wk + r*DIM + k4);
    }
    CP_COMMIT();
    CP_WAIT1();   // As + W0 arrived
    #pragma unroll
    for (int j = 0; j < 16; j++) {
        int c = tid + j*256;
        int r = c >> 5, k4 = (c & 31) * 4;
        float4* p = (float4*)(As + r*PADK + k4);
        float4 v = *p;
        v.x = tf32_round(v.x); v.y = tf32_round(v.y);
        v.z = tf32_round(v.z); v.w = tf32_round(v.w);
        *p = v;
        float4* q = (float4*)(Wb[0] + r*PADK + k4);
        v = *q;
        v.x = tf32_round(v.x); v.y = tf32_round(v.y);
        v.z = tf32_round(v.z); v.w = tf32_round(v.w);
        *q = v;
    }
    __syncthreads();

    const int lane = tid & 31, warp = tid >> 5;
    const int wm = (warp >> 1) * 32;
    const int wn = (warp & 1) * 64;
    const int g = lane >> 2, t = lane & 3;

    #pragma unroll 1
    for (int z = 0; z < 3; z++) {
        float* Bs = Wb[z == 1];
        const float* bias = (z == 0) ? bq : (z == 1) ? bk : bv;

        float c[2][8][4];
        #pragma unroll
        for (int mt = 0; mt < 2; mt++)
            #pragma unroll
            for (int nt = 0; nt < 8; nt++)
                #pragma unroll
                for (int j = 0; j < 4; j++) c[mt][nt][j] = 0.0f;

        #pragma unroll
        for (int kk = 0; kk < DIM/8; kk++) {
            const int kb = kk*8;
            uint32_t a[2][4], bb[8][2];
            #pragma unroll
            for (int mt = 0; mt < 2; mt++) {
                const float* p = As + (wm + mt*16 + g)*PADK + kb + t;
                a[mt][0] = __float_as_uint(p[0]);
                a[mt][1] = __float_as_uint(p[8*PADK]);
                a[mt][2] = __float_as_uint(p[4]);
                a[mt][3] = __float_as_uint(p[8*PADK + 4]);
            }
            #pragma unroll
            for (int nt = 0; nt < 8; nt++) {
                const float* p = Bs + (wn + nt*8 + g)*PADK + kb + t;
                bb[nt][0] = __float_as_uint(p[0]);
                bb[nt][1] = __float_as_uint(p[4]);
            }
            #pragma unroll
            for (int mt = 0; mt < 2; mt++)
                #pragma unroll
                for (int nt = 0; nt < 8; nt++)
                    MMA_TF32(c[mt][nt], a[mt], bb[nt]);
        }

        const float scale = (z == 0) ? LOG2E : 1.0f;
        __half* oh = (z == 0) ? g_Qh : g_Kh;
        #pragma unroll
        for (int mt = 0; mt < 2; mt++) {
            const int r0 = rowBase + wm + mt*16 + g;
            #pragma unroll
            for (int nt = 0; nt < 8; nt++) {
                const int cn = wn + nt*8 + 2*t;
                float b0 = __ldg(&bias[cn]), b1 = __ldg(&bias[cn+1]);
                float v00 = (c[mt][nt][0] + b0) * scale, v01 = (c[mt][nt][1] + b1) * scale;
                float v10 = (c[mt][nt][2] + b0) * scale, v11 = (c[mt][nt][3] + b1) * scale;
                if (z < 2) {
                    *(__half2*)(oh + (size_t)r0*DIM + cn)     = __floats2half2_rn(v00, v01);
                    *(__half2*)(oh + (size_t)(r0+8)*DIM + cn) = __floats2half2_rn(v10, v11);
                } else {
                    *(float2*)(g_V + (size_t)r0*DIM + cn)     = make_float2(v00, v01);
                    *(float2*)(g_V + (size_t)(r0+8)*DIM + cn) = make_float2(v10, v11);
                }
            }
        }

        if (z == 0) {
            __syncthreads();
            #pragma unroll
            for (int j = 0; j < 16; j++) {
                int cc = tid + j*256;
                int r = cc >> 5, k4 = (cc & 31) * 4;
                CP_ASYNC16((uint32_t)__cvta_generic_to_shared(Wb[0] + r*PADK + k4),
                           Wv + r*DIM + k4);
            }
            CP_COMMIT();
            CP_WAIT1();                         // W1 (Wk) arrived
            #pragma unroll
            for (int j = 0; j < 16; j++) {
                int cc = tid + j*256;
                int r = cc >> 5, k4 = (cc & 31) * 4;
                float4* p = (float4*)(Wb[1] + r*PADK + k4);
                float4 v = *p;
                v.x = tf32_round(v.x); v.y = tf32_round(v.y);
                v.z = tf32_round(v.z); v.w = tf32_round(v.w);
                *p = v;
            }
            __syncthreads();
        } else if (z == 1) {
            __syncthreads();
            CP_WAIT0();                         // Wv arrived
            #pragma unroll
            for (int j = 0; j < 16; j++) {
                int cc = tid + j*256;
                int r = cc >> 5, k4 = (cc & 31) * 4;
                float4* p = (float4*)(Wb[0] + r*PADK + k4);
                float4 v = *p;
                v.x = tf32_round(v.x); v.y = tf32_round(v.y);
                v.z = tf32_round(v.z); v.w = tf32_round(v.w);
                *p = v;
            }
            __syncthreads();
        }
    }
}

// ---------------- K2: E = 2^(Q'K^T) (fp16 mma + ldmatrix), rowsums -----------
// Each block handles TWO adjacent 128-col tiles against one resident Q tile.
// Second K tile prefetched via cp.async overlapped with first tile's E-flush.
__global__ __launch_bounds__(256, 2)
void score_kernel() {
    extern __shared__ __half smh[];
    __half* Qs = smh;             // [BM][SB]
    __half* Ks = smh +   BM*SB;   // [BN][SB]
    __nv_bfloat16* Es = (__nv_bfloat16*)(smh + 2*BM*SB);   // [BM][SB] staging

    const int b = blockIdx.z;
    const int rowBase = blockIdx.y * BM;
    const int colBase0 = blockIdx.x * (2*BN);
    const int tid = threadIdx.x;

    {
        const uint4* Qg = (const uint4*)(g_Qh + ((size_t)b*SEQ + rowBase)*DIM);
        const uint4* Kg = (const uint4*)(g_Kh + ((size_t)b*SEQ + colBase0)*DIM);
        #pragma unroll
        for (int i = tid; i < BM*16; i += 256) {
            int r = i >> 4, ch = i & 15;
            *(uint4*)(Qs + r*SB + ch*8) = Qg[r*16 + ch];
            *(uint4*)(Ks + r*SB + ch*8) = Kg[r*16 + ch];
        }
    }
    __syncthreads();

    const int lane = tid & 31, warp = tid >> 5;
    const int wm = (warp >> 1) * 32;
    const int wn = (warp & 1) * 64;

    const int aRow = wm + (lane & 15);
    const int aCol = (lane >> 4) << 3;
    uint32_t aAddr = (uint32_t)__cvta_generic_to_shared(Qs + aRow*SB + aCol);
    const int bRow = wn + (lane & 7) + ((lane >> 4) << 3);
    const int bCol = ((lane >> 3) & 1) << 3;
    uint32_t bAddr = (uint32_t)__cvta_generic_to_shared(Ks + bRow*SB + bCol);
    const uint32_t ksBase = (uint32_t)__cvta_generic_to_shared(Ks);

    const int g = lane >> 2, t = lane & 3;

    #pragma unroll 1
    for (int ct = 0; ct < 2; ct++) {
        const int colBase = colBase0 + ct*BN;

        float c[2][8][4];
        #pragma unroll
        for (int mt = 0; mt < 2; mt++)
            #pragma unroll
            for (int nt = 0; nt < 8; nt++)
                #pragma unroll
                for (int j = 0; j < 4; j++) c[mt][nt][j] = 0.0f;

        #pragma unroll
        for (int kk = 0; kk < DIM/16; kk++) {
            uint32_t a[2][4], bb[4][4];
            #pragma unroll
            for (int mt = 0; mt < 2; mt++)
                LDMX4(a[mt], aAddr + (mt*16*SB)*2 + kk*32);
            #pragma unroll
            for (int ntp = 0; ntp < 4; ntp++)
                LDMX4(bb[ntp], bAddr + (ntp*16*SB)*2 + kk*32);
            #pragma unroll
            for (int mt = 0; mt < 2; mt++)
                #pragma unroll
                for (int nt = 0; nt < 8; nt++)
                    MMA_FP16(c[mt][nt], a[mt], bb[nt>>1][(nt&1)*2], bb[nt>>1][(nt&1)*2+1]);
        }

        // epilogue: ex2, rowsum, stage bf16 tile in smem (conflict-free STS)
        #pragma unroll
        for (int mt = 0; mt < 2; mt++) {
            const int lr0 = wm + mt*16 + g;       // tile-local rows
            const int lr1 = lr0 + 8;
            float rs0 = 0.0f, rs1 = 0.0f;
            #pragma unroll
            for (int nt = 0; nt < 8; nt++) {
                const int cn = wn + nt*8 + 2*t;
                float e0 = ex2f(c[mt][nt][0]);
                float e1 = ex2f(c[mt][nt][1]);
                float e2 = ex2f(c[mt][nt][2]);
                float e3 = ex2f(c[mt][nt][3]);
                rs0 += e0 + e1;
                rs1 += e2 + e3;
                *(__nv_bfloat162*)(Es + lr0*SB + cn) = __floats2bfloat162_rn(e0, e1);
                *(__nv_bfloat162*)(Es + lr1*SB + cn) = __floats2bfloat162_rn(e2, e3);
            }
            #pragma unroll
            for (int o = 1; o <= 2; o <<= 1) {
                rs0 += __shfl_xor_sync(0xffffffffu, rs0, o);
                rs1 += __shfl_xor_sync(0xffffffffu, rs1, o);
            }
            if (t == 0) {
                atomicAdd(&g_S[b*SEQ + rowBase + lr0], rs0);
                atomicAdd(&g_S[b*SEQ + rowBase + lr1], rs1);
            }
        }
        __syncthreads();   // Es complete; all warps done reading Ks (mma finished)

        // prefetch second K tile (overlaps the E-flush below; disjoint buffers)
        if (ct == 0) {
            const __half* Kn = g_Kh + ((size_t)b*SEQ + colBase0 + BN)*DIM;
            #pragma unroll
            for (int j = 0; j < 8; j++) {
                int idx = tid + j*256;
                int r = idx >> 4, ch = idx & 15;
                CP_ASYNC16(ksBase + (uint32_t)(r*SB + ch*8)*2,
                           Kn + (size_t)r*DIM + ch*8);
            }
            CP_COMMIT();
        }

        // coalesced flush: 2048 uint4 / 256 threads = 8 per thread
        #pragma unroll
        for (int j = 0; j < 8; j++) {
            int idx = tid + j*256;
            int r = idx >> 4, ch = idx & 15;
            uint4 v = *(const uint4*)(Es + r*SB + ch*8);
            *(uint4*)(g_E + ((size_t)b*SEQ + rowBase + r)*SEQ + colBase + ch*8) = v;
        }

        if (ct == 0) {
            CP_WAIT0();
            __syncthreads();   // new Ks visible; Es reusable (flush done per-thread)
        }
    }
}

// ---------------- K3: column-tiled colsum (R4 version, 29.4us measured) ------
#define K3_ROWS 256
__global__ __launch_bounds__(256, 8)
void colsum_kernel() {
    __shared__ float invS[K3_ROWS];
    const int b = blockIdx.z;
    const int mBase = blockIdx.x * 512;          // 512 m's per block (2 per thread)
    const int nBase = blockIdx.y * K3_ROWS;
    const int tid = threadIdx.x;

    if (tid < K3_ROWS) invS[tid] = 1.0f / g_S[b*SEQ + nBase + tid];
    __syncthreads();

    const __nv_bfloat162* Ep =
        (const __nv_bfloat162*)(g_E + ((size_t)b*SEQ + nBase)*SEQ) + (mBase >> 1) + tid;
    const size_t strideV2 = SEQ / 2;

    float a0 = 0.f, a1 = 0.f, b0 = 0.f, b1 = 0.f;
    #pragma unroll 8
    for (int n = 0; n < K3_ROWS; n += 2) {
        float2 v0 = __bfloat1622float2(Ep[(size_t)n * strideV2]);
        float2 v1 = __bfloat1622float2(Ep[(size_t)(n+1) * strideV2]);
        a0 += v0.x * invS[n];   a1 += v0.y * invS[n];
        b0 += v1.x * invS[n+1]; b1 += v1.y * invS[n+1];
    }
    const int m = mBase + tid*2;
    atomicAdd(&g_C[b*SEQ + m],     (a0 + b0) * (1.0f/SEQ));
    atomicAdd(&g_C[b*SEQ + m + 1], (a1 + b1) * (1.0f/SEQ));
}

// ---------------- K4: out[b,d] = sum_m c[m] * V[b,m,d] -----------------------
// 512 blocks x 512 threads: 4 row-groups per block, smem tree reduction,
// one global atomic per (block, d).
__global__ __launch_bounds__(512, 4)
void out_kernel(float* __restrict__ out) {
    __shared__ float sred[3*DIM];
    const int b = blockIdx.y;
    const int mBase = blockIdx.x * 32;
    const int d = threadIdx.x & 127;
    const int h = threadIdx.x >> 7;     // 0..3
    const float* Vp = g_V + ((size_t)b*SEQ + mBase + h)*DIM + d;
    const float* Cp = g_C + b*SEQ + mBase + h;
    float acc = 0.0f;
    #pragma unroll
    for (int m = 0; m < 32; m += 4)
        acc += Cp[m] * Vp[(size_t)m*DIM];
    if (h) sred[(h-1)*DIM + d] = acc;
    __syncthreads();
    if (h == 0)
        atomicAdd(&out[b*DIM + d], acc + sred[d] + sred[DIM + d] + sred[2*DIM + d]);
}

// ---------------- launch -----------------------------------------------------
extern "C" void kernel_launch(void* const* d_in, const int* in_sizes, int n_in,
                              void* d_out, int out_size) {
    const float* x  = (const float*)d_in[0];
    const float* Wq = (const float*)d_in[1];
    const float* bq = (const float*)d_in[2];
    const float* Wk = (const float*)d_in[3];
    const float* bk = (const float*)d_in[4];
    const float* Wv = (const float*)d_in[5];
    const float* bv = (const float*)d_in[6];
    float* out = (float*)d_out;

    const int smemProj  = 3 * BM * PADK * sizeof(float);   // 202752 B
    const int smemScore = 3 * BM * SB * sizeof(__half);    // 104448 B
    cudaFuncSetAttribute(proj_kernel,  cudaFuncAttributeMaxDynamicSharedMemorySize, smemProj);
    cudaFuncSetAttribute(score_kernel, cudaFuncAttributeMaxDynamicSharedMemorySize, smemScore);

    proj_kernel<<<TOK/BM, 256, smemProj>>>(x, Wq, bq, Wk, bk, Wv, bv, out);

    dim3 gScore(SEQ/(2*BN), SEQ/BM, BATCH);  // 16 x 32 x 4 = 2048 blocks
    score_kernel<<<gScore, 256, smemScore>>>();

    dim3 gCol(SEQ/512, SEQ/K3_ROWS, BATCH);  // 8 x 16 x 4
    colsum_kernel<<<gCol, 256>>>();

    dim3 gOut(SEQ/32, BATCH);                // 128 x 4 = 512 blocks
    out_kernel<<<gOut, 512>>>(out);
}